// round 8
// baseline (speedup 1.0000x reference)
#include <cuda_runtime.h>
#include <cuda_bf16.h>
#include <math.h>
#include <stdint.h>

#define T_STEPS 64
#define BATCH   1024
#define HID     512
#define VOCAB   512
#define G4H     2048

typedef __nv_bfloat16 bf16;
typedef unsigned long long u64;

// ---------------------------------------------------------------------------
// Device-global scratch (allocation-free)
// ---------------------------------------------------------------------------
__device__ float g_c[BATCH * HID];            // cell state fp32
__device__ bf16  g_hs[2][3][BATCH * HID];     // h 3-way splits, ping-pong
__device__ bf16  g_Wih[3][G4H * HID];         // gate-interleaved W_ih splits
__device__ bf16  g_Whh[3][G4H * HID];         // gate-interleaved W_hh splits
__device__ bf16  g_Wo[3][VOCAB * HID];        // W_out splits
__device__ bf16  g_emb[3][VOCAB * HID];       // embedding splits
__device__ float g_bias[G4H];                 // gate-interleaved b_ih+b_hh
__device__ float g_E[VOCAB * G4H];            // emb @ W_ih^T + bias (fp32)
__device__ u64   g_amax[2][BATCH];            // packed (mapped logit, 511-col)

// ---------------------------------------------------------------------------
// Helpers
// ---------------------------------------------------------------------------
__device__ __forceinline__ uint32_t smem_u32(const void* p) {
    uint32_t a;
    asm("{ .reg .u64 t; cvta.to.shared.u64 t, %1; cvt.u32.u64 %0, t; }"
        : "=r"(a) : "l"(p));
    return a;
}

#define SWZ64(x) ((x) ^ (((x) >> 3) & 0x30))

__device__ __forceinline__ void cp16(uint32_t dst, const void* src) {
    asm volatile("cp.async.cg.shared.global [%0], [%1], 16;" :: "r"(dst), "l"(src));
}

__device__ __forceinline__ void ldsm4(uint32_t& r0, uint32_t& r1,
                                      uint32_t& r2, uint32_t& r3, uint32_t addr) {
    asm volatile("ldmatrix.sync.aligned.m8n8.x4.shared.b16 {%0,%1,%2,%3}, [%4];"
                 : "=r"(r0), "=r"(r1), "=r"(r2), "=r"(r3) : "r"(addr));
}

__device__ __forceinline__ void mma_bf16(float c[4], const uint32_t a[4],
                                         const uint32_t b[2]) {
    asm volatile(
        "mma.sync.aligned.m16n8k16.row.col.f32.bf16.bf16.f32 "
        "{%0,%1,%2,%3}, {%4,%5,%6,%7}, {%8,%9}, {%0,%1,%2,%3};"
        : "+f"(c[0]), "+f"(c[1]), "+f"(c[2]), "+f"(c[3])
        : "r"(a[0]), "r"(a[1]), "r"(a[2]), "r"(a[3]), "r"(b[0]), "r"(b[1]));
}

// Exact 3-way bf16 split
__device__ __forceinline__ void split3(float v, bf16& s0, bf16& s1, bf16& s2) {
    s0 = __float2bfloat16(v);
    float r = v - __bfloat162float(s0);
    s1 = __float2bfloat16(r);
    float r2 = r - __bfloat162float(s1);
    s2 = __float2bfloat16(r2);
}

// Monotone float->u32 map; key packs (value, 511-col) for first-max argmax
__device__ __forceinline__ u64 amax_key(float v, int col) {
    uint32_t u = __float_as_uint(v);
    uint32_t mu = (u & 0x80000000u) ? ~u : (u | 0x80000000u);
    return ((u64)mu << 32) | (uint32_t)(511 - col);
}

// ---------------------------------------------------------------------------
// Prep kernels
// ---------------------------------------------------------------------------
__global__ void prep_gates(const float* __restrict__ Wih, const float* __restrict__ Whh,
                           const float* __restrict__ bih, const float* __restrict__ bhh) {
    int idx = blockIdx.x * blockDim.x + threadIdx.x;    // [0, G4H*HID)
    int n = idx >> 9;
    int k = idx & 511;
    int orig = ((n & 3) << 9) + (n >> 2);               // interleave i,f,g,o per j
    split3(Wih[(size_t)orig * 512 + k], g_Wih[0][idx], g_Wih[1][idx], g_Wih[2][idx]);
    split3(Whh[(size_t)orig * 512 + k], g_Whh[0][idx], g_Whh[1][idx], g_Whh[2][idx]);
    if (k == 0) g_bias[n] = bih[orig] + bhh[orig];
}

__global__ void prep_out(const float* __restrict__ Wout, const float* __restrict__ emb) {
    int idx = blockIdx.x * blockDim.x + threadIdx.x;    // [0, VOCAB*HID)
    split3(Wout[idx], g_Wo[0][idx], g_Wo[1][idx], g_Wo[2][idx]);
    split3(emb[idx], g_emb[0][idx], g_emb[1][idx], g_emb[2][idx]);
}

__global__ void init_state_tc(const float* __restrict__ ench,
                              const float* __restrict__ encc) {
    int idx = blockIdx.x * blockDim.x + threadIdx.x;    // [0, BATCH*HID)
    g_c[idx] = encc[idx];
    split3(ench[idx], g_hs[0][0][idx], g_hs[0][1][idx], g_hs[0][2][idx]);
    if ((idx & 511) == 0) g_amax[1][idx >> 9] = 511ull;  // decodes to SOS token 0
}

// ---------------------------------------------------------------------------
// Shared GEMM machinery.  CTA = 128 threads (4 warps, 2Mx2N), warp tile
// (MF*16) x 32.  A tile rows = MF*32, B tile rows = 64.  K-chunk 32 (SW64,
// 64B rows), double-buffered cp.async.  One A-split live at a time.
// ---------------------------------------------------------------------------
#define STAGE_BYTES(MF)  (3 * (MF) * 2048 + 12288)   // 3 A tiles + 3 B tiles
#define SMEM_OF(MF)      (2 * STAGE_BYTES(MF) + 1024)

template<int MF>
__device__ __forceinline__ void load_st(uint32_t st, int tid,
                                        const bf16* const* srcs, int koff) {
#pragma unroll
    for (int s = 0; s < 3; s++)
#pragma unroll
        for (int j = 0; j < MF; j++) {        // A split: MF*32 rows x 4 units
            int u = tid + j * 128;
            int row = u >> 2, c = u & 3;
            cp16(st + s * (MF * 2048) + SWZ64(row * 64 + c * 16),
                 srcs[s] + (size_t)row * 512 + koff + c * 8);
        }
#pragma unroll
    for (int s = 0; s < 3; s++)
#pragma unroll
        for (int j = 0; j < 2; j++) {         // B split: 64 rows x 4 units
            int u = tid + j * 128;
            int row = u >> 2, c = u & 3;
            cp16(st + 3 * MF * 2048 + s * 4096 + SWZ64(row * 64 + c * 16),
                 srcs[3 + s] + (size_t)row * 512 + koff + c * 8);
        }
    asm volatile("cp.async.commit_group;" ::: "memory");
}

template<int MF>
__device__ __forceinline__ void mainloop_t(uint32_t smem, int tid,
                                           const bf16* const* srcs,
                                           float C[MF][4][4]) {
    const int STG = STAGE_BYTES(MF);
    const int l = tid & 31, wid = tid >> 5;
    const int wm = wid >> 1, wn = wid & 1;
    const int a_row = l & 15;
    const int a_cb  = (l >> 4) << 4;
    const int b_row = (((l >> 4) & 1) << 3) + (l & 7);
    const int b_cb  = ((l >> 3) & 1) << 4;

    load_st<MF>(smem, tid, srcs, 0);

#pragma unroll 1
    for (int ch = 0; ch < 16; ch++) {
        uint32_t cur = smem + (ch & 1) * STG;
        if (ch < 15) {
            load_st<MF>(smem + ((ch + 1) & 1) * STG, tid, srcs, (ch + 1) * 32);
            asm volatile("cp.async.wait_group 1;" ::: "memory");
        } else {
            asm volatile("cp.async.wait_group 0;" ::: "memory");
        }
        __syncthreads();

#pragma unroll
        for (int ks = 0; ks < 2; ks++) {
            uint32_t B[3][4][2];
#pragma unroll
            for (int s = 0; s < 3; s++)
#pragma unroll
                for (int nh = 0; nh < 2; nh++) {
                    uint32_t ad = cur + 3 * MF * 2048 + s * 4096 +
                        SWZ64((wn * 32 + nh * 16 + b_row) * 64 + ks * 32 + b_cb);
                    uint32_t r0, r1, r2, r3;
                    ldsm4(r0, r1, r2, r3, ad);
                    B[s][nh * 2][0] = r0; B[s][nh * 2][1] = r1;
                    B[s][nh * 2 + 1][0] = r2; B[s][nh * 2 + 1][1] = r3;
                }
#pragma unroll
            for (int sa = 0; sa < 3; sa++) {
                uint32_t A[MF][4];
#pragma unroll
                for (int mf = 0; mf < MF; mf++) {
                    uint32_t ad = cur + sa * (MF * 2048) +
                        SWZ64((wm * (MF * 16) + mf * 16 + a_row) * 64 + ks * 32 + a_cb);
                    ldsm4(A[mf][0], A[mf][1], A[mf][2], A[mf][3], ad);
                }
#pragma unroll
                for (int sb = 0; sb < 3 - sa; sb++)
#pragma unroll
                    for (int mf = 0; mf < MF; mf++)
#pragma unroll
                        for (int nf = 0; nf < 4; nf++)
                            mma_bf16(C[mf][nf], A[mf], B[sb][nf]);
            }
        }
        __syncthreads();
    }
}

// ---------------------------------------------------------------------------
// prep_E: E = emb @ W_ih^T + bias.  Tile 128x64, grid (32, 4)
// ---------------------------------------------------------------------------
__global__ __launch_bounds__(128, 2) void prep_E_kernel() {
    extern __shared__ char dsm[];
    uint32_t smem = (smem_u32(dsm) + 1023) & ~1023u;
    int tid = threadIdx.x;
    int l = tid & 31, wid = tid >> 5;
    int wm = wid >> 1, wn = wid & 1, tg = l & 3;
    int n0 = blockIdx.x * 64, m0 = blockIdx.y * 128;

    const bf16* srcs[6] = {
        g_emb[0] + (size_t)m0 * 512, g_emb[1] + (size_t)m0 * 512,
        g_emb[2] + (size_t)m0 * 512,
        g_Wih[0] + (size_t)n0 * 512, g_Wih[1] + (size_t)n0 * 512,
        g_Wih[2] + (size_t)n0 * 512};

    float C[4][4][4] = {};
    mainloop_t<4>(smem, tid, srcs, C);

#pragma unroll
    for (int mf = 0; mf < 4; mf++)
#pragma unroll
        for (int nf = 0; nf < 4; nf++) {
            int n = n0 + wn * 32 + nf * 8 + tg * 2;
#pragma unroll
            for (int rh = 0; rh < 2; rh++) {
                int m = m0 + wm * 64 + mf * 16 + (l >> 2) + rh * 8;
                float2 v = make_float2(C[mf][nf][rh * 2 + 0] + g_bias[n],
                                       C[mf][nf][rh * 2 + 1] + g_bias[n + 1]);
                *(float2*)&g_E[(size_t)m * G4H + n] = v;
            }
        }
}

// ---------------------------------------------------------------------------
// Gates: gates = h @ W_hh^T (+ E[token] in epilogue) -> fused LSTM cell
// Tile 128x64, grid (32, 8).  rd = h read buffer (t&1).
// Reads token from g_amax[rd^1]; clears g_amax[rd] for this step's logits.
// ---------------------------------------------------------------------------
__global__ __launch_bounds__(128, 2) void gates_tc(int rd) {
    extern __shared__ char dsm[];
    uint32_t smem = (smem_u32(dsm) + 1023) & ~1023u;
    int tid = threadIdx.x;
    int l = tid & 31, wid = tid >> 5;
    int wm = wid >> 1, wn = wid & 1, tg = l & 3;
    int n0 = blockIdx.x * 64, m0 = blockIdx.y * 128;
    int wr = rd ^ 1;

    g_amax[rd][m0 + tid] = 0ull;   // clear argmax buffer for this step

    const bf16* srcs[6] = {
        g_hs[rd][0] + (size_t)m0 * 512, g_hs[rd][1] + (size_t)m0 * 512,
        g_hs[rd][2] + (size_t)m0 * 512,
        g_Whh[0] + (size_t)n0 * 512, g_Whh[1] + (size_t)n0 * 512,
        g_Whh[2] + (size_t)n0 * 512};

    float C[4][4][4] = {};
    mainloop_t<4>(smem, tid, srcs, C);

    // Epilogue: even-tg lane holds (i,f) pre-acts; partner (tg^1) holds (g,o).
#pragma unroll
    for (int mf = 0; mf < 4; mf++)
#pragma unroll
        for (int rh = 0; rh < 2; rh++) {
            int m = m0 + wm * 64 + mf * 16 + (l >> 2) + rh * 8;
            int tok = 511 - (int)(g_amax[wr][m] & 0x3ffull);
            const float* Erow = g_E + (size_t)tok * G4H;
#pragma unroll
            for (int nf = 0; nf < 4; nf++) {
                float own0 = C[mf][nf][rh * 2 + 0];
                float own1 = C[mf][nf][rh * 2 + 1];
                float p0 = __shfl_xor_sync(0xffffffffu, own0, 1);
                float p1 = __shfl_xor_sync(0xffffffffu, own1, 1);
                if (!(tg & 1)) {
                    int n = n0 + wn * 32 + nf * 8 + tg * 2;   // = 4*j
                    int j = n >> 2;
                    float4 e = *(const float4*)&Erow[n];
                    float gi = own0 + e.x;
                    float gf = own1 + e.y;
                    float gg = p0 + e.z;
                    float go = p1 + e.w;
                    float is = 1.f / (1.f + expf(-gi));
                    float fs = 1.f / (1.f + expf(-gf));
                    float os = 1.f / (1.f + expf(-go));
                    size_t hx = (size_t)m * HID + j;
                    float cn = fs * g_c[hx] + is * tanhf(gg);
                    g_c[hx] = cn;
                    float hn = os * tanhf(cn);
                    split3(hn, g_hs[wr][0][hx], g_hs[wr][1][hx], g_hs[wr][2][hx]);
                }
            }
        }
}

// ---------------------------------------------------------------------------
// Logits: out = h @ W_out^T + b_out, fused per-row argmax via atomicMax.
// Tile 64x64, grid (8, 16).  ph = h buffer to read; ab = amax buffer to write.
// ---------------------------------------------------------------------------
__global__ __launch_bounds__(128, 2) void logits_tc(int ph, int ab,
                                                    const float* __restrict__ bo,
                                                    float* __restrict__ out_t) {
    extern __shared__ char dsm[];
    uint32_t smem = (smem_u32(dsm) + 1023) & ~1023u;
    int tid = threadIdx.x;
    int l = tid & 31, wid = tid >> 5;
    int wm = wid >> 1, wn = wid & 1, tg = l & 3;
    int n0 = blockIdx.x * 64, m0 = blockIdx.y * 64;

    const bf16* srcs[6] = {
        g_hs[ph][0] + (size_t)m0 * 512, g_hs[ph][1] + (size_t)m0 * 512,
        g_hs[ph][2] + (size_t)m0 * 512,
        g_Wo[0] + (size_t)n0 * 512, g_Wo[1] + (size_t)n0 * 512,
        g_Wo[2] + (size_t)n0 * 512};

    float C[2][4][4] = {};
    mainloop_t<2>(smem, tid, srcs, C);

#pragma unroll
    for (int mf = 0; mf < 2; mf++)
#pragma unroll
        for (int rh = 0; rh < 2; rh++) {
            int m = m0 + wm * 32 + mf * 16 + (l >> 2) + rh * 8;
            u64 best = 0ull;
#pragma unroll
            for (int nf = 0; nf < 4; nf++) {
                int n = n0 + wn * 32 + nf * 8 + tg * 2;
                float v0 = C[mf][nf][rh * 2 + 0] + bo[n];
                float v1 = C[mf][nf][rh * 2 + 1] + bo[n + 1];
                *(float2*)&out_t[(size_t)m * VOCAB + n] = make_float2(v0, v1);
                u64 k0 = amax_key(v0, n), k1 = amax_key(v1, n + 1);
                if (k0 > best) best = k0;
                if (k1 > best) best = k1;
            }
            u64 o1 = __shfl_xor_sync(0xffffffffu, best, 1);
            if (o1 > best) best = o1;
            u64 o2 = __shfl_xor_sync(0xffffffffu, best, 2);
            if (o2 > best) best = o2;
            if (tg == 0) atomicMax(&g_amax[ab][m], best);
        }
}

// ---------------------------------------------------------------------------
// Launch
// ---------------------------------------------------------------------------
extern "C" void kernel_launch(void* const* d_in, const int* in_sizes, int n_in,
                              void* d_out, int out_size) {
    const float* enc_h = (const float*)d_in[2];
    const float* enc_c = (const float*)d_in[3];
    const float* emb   = (const float*)d_in[4];
    const float* W_ih  = (const float*)d_in[5];
    const float* W_hh  = (const float*)d_in[6];
    const float* b_ih  = (const float*)d_in[7];
    const float* b_hh  = (const float*)d_in[8];
    const float* W_out = (const float*)d_in[9];
    const float* b_out = (const float*)d_in[10];
    float* out = (float*)d_out;

    const int GSM = SMEM_OF(4);   // 74752
    const int LSM = SMEM_OF(2);   // 50176
    cudaFuncSetAttribute(prep_E_kernel, cudaFuncAttributeMaxDynamicSharedMemorySize, GSM);
    cudaFuncSetAttribute(gates_tc, cudaFuncAttributeMaxDynamicSharedMemorySize, GSM);
    cudaFuncSetAttribute(logits_tc, cudaFuncAttributeMaxDynamicSharedMemorySize, LSM);

    prep_gates<<<(G4H * HID) / 256, 256>>>(W_ih, W_hh, b_ih, b_hh);
    prep_out<<<(VOCAB * HID) / 256, 256>>>(W_out, emb);
    init_state_tc<<<(BATCH * HID) / 256, 256>>>(enc_h, enc_c);
    prep_E_kernel<<<dim3(32, 4), 128, GSM>>>();

    for (int t = 0; t < T_STEPS; t++) {
        int rd = t & 1;
        gates_tc<<<dim3(32, 8), 128, GSM>>>(rd);
        float* logits_t = out + (size_t)t * BATCH * VOCAB;
        logits_tc<<<dim3(8, 16), 128, LSM>>>(rd ^ 1, rd, b_out, logits_t);
    }
}

// round 10
// speedup vs baseline: 1.0458x; 1.0458x over previous
#include <cuda_runtime.h>
#include <cuda_bf16.h>
#include <math.h>
#include <stdint.h>

#define T_STEPS 64
#define BATCH   1024
#define HID     512
#define VOCAB   512
#define G4H     2048

typedef __nv_bfloat16 bf16;
typedef unsigned long long u64;

// ---------------------------------------------------------------------------
// Device-global scratch (allocation-free)
// ---------------------------------------------------------------------------
__device__ float g_c[BATCH * HID];            // cell state fp32
__device__ bf16  g_hs[2][3][BATCH * HID];     // h 3-way splits, ping-pong
__device__ bf16  g_Wih[3][G4H * HID];         // gate-interleaved W_ih splits
__device__ bf16  g_Whh[3][G4H * HID];         // gate-interleaved W_hh splits
__device__ bf16  g_Wo[3][VOCAB * HID];        // W_out splits
__device__ bf16  g_emb[3][VOCAB * HID];       // embedding splits
__device__ float g_bias[G4H];                 // gate-interleaved b_ih+b_hh
__device__ float g_E[VOCAB * G4H];            // emb @ W_ih^T + bias (fp32)
__device__ u64   g_amax[2][BATCH];            // packed (mapped logit, 511-col)

// ---------------------------------------------------------------------------
// Helpers
// ---------------------------------------------------------------------------
__device__ __forceinline__ uint32_t smem_u32(const void* p) {
    uint32_t a;
    asm("{ .reg .u64 t; cvta.to.shared.u64 t, %1; cvt.u32.u64 %0, t; }"
        : "=r"(a) : "l"(p));
    return a;
}

#define SWZ64(x) ((x) ^ (((x) >> 3) & 0x30))

__device__ __forceinline__ void cp16(uint32_t dst, const void* src) {
    asm volatile("cp.async.cg.shared.global [%0], [%1], 16;" :: "r"(dst), "l"(src));
}

__device__ __forceinline__ void ldsm4(uint32_t& r0, uint32_t& r1,
                                      uint32_t& r2, uint32_t& r3, uint32_t addr) {
    asm volatile("ldmatrix.sync.aligned.m8n8.x4.shared.b16 {%0,%1,%2,%3}, [%4];"
                 : "=r"(r0), "=r"(r1), "=r"(r2), "=r"(r3) : "r"(addr));
}

__device__ __forceinline__ void mma_bf16(float c[4], const uint32_t a[4],
                                         const uint32_t b[2]) {
    asm volatile(
        "mma.sync.aligned.m16n8k16.row.col.f32.bf16.bf16.f32 "
        "{%0,%1,%2,%3}, {%4,%5,%6,%7}, {%8,%9}, {%0,%1,%2,%3};"
        : "+f"(c[0]), "+f"(c[1]), "+f"(c[2]), "+f"(c[3])
        : "r"(a[0]), "r"(a[1]), "r"(a[2]), "r"(a[3]), "r"(b[0]), "r"(b[1]));
}

// Exact 3-way bf16 split
__device__ __forceinline__ void split3(float v, bf16& s0, bf16& s1, bf16& s2) {
    s0 = __float2bfloat16(v);
    float r = v - __bfloat162float(s0);
    s1 = __float2bfloat16(r);
    float r2 = r - __bfloat162float(s1);
    s2 = __float2bfloat16(r2);
}

// Monotone float->u32 map; key packs (value, 511-col) for first-max argmax
__device__ __forceinline__ u64 amax_key(float v, int col) {
    uint32_t u = __float_as_uint(v);
    uint32_t mu = (u & 0x80000000u) ? ~u : (u | 0x80000000u);
    return ((u64)mu << 32) | (uint32_t)(511 - col);
}

// ---------------------------------------------------------------------------
// Prep kernels
// ---------------------------------------------------------------------------
__global__ void prep_gates(const float* __restrict__ Wih, const float* __restrict__ Whh,
                           const float* __restrict__ bih, const float* __restrict__ bhh) {
    int idx = blockIdx.x * blockDim.x + threadIdx.x;    // [0, G4H*HID)
    int n = idx >> 9;
    int k = idx & 511;
    int orig = ((n & 3) << 9) + (n >> 2);               // interleave i,f,g,o per j
    split3(Wih[(size_t)orig * 512 + k], g_Wih[0][idx], g_Wih[1][idx], g_Wih[2][idx]);
    split3(Whh[(size_t)orig * 512 + k], g_Whh[0][idx], g_Whh[1][idx], g_Whh[2][idx]);
    if (k == 0) g_bias[n] = bih[orig] + bhh[orig];
}

__global__ void prep_out(const float* __restrict__ Wout, const float* __restrict__ emb) {
    int idx = blockIdx.x * blockDim.x + threadIdx.x;    // [0, VOCAB*HID)
    split3(Wout[idx], g_Wo[0][idx], g_Wo[1][idx], g_Wo[2][idx]);
    split3(emb[idx], g_emb[0][idx], g_emb[1][idx], g_emb[2][idx]);
}

__global__ void init_state_tc(const float* __restrict__ ench,
                              const float* __restrict__ encc) {
    int idx = blockIdx.x * blockDim.x + threadIdx.x;    // [0, BATCH*HID)
    g_c[idx] = encc[idx];
    split3(ench[idx], g_hs[0][0][idx], g_hs[0][1][idx], g_hs[0][2][idx]);
    if ((idx & 511) == 0) g_amax[1][idx >> 9] = 511ull;  // decodes to SOS token 0
}

// ---------------------------------------------------------------------------
// GEMM machinery.  CTA = 256 threads, 8 warps (2M x 4N).
// Warp tile (MF*16) x (NF*8).  CTA tile (MF*32) x (NF*32).
// K-chunk 32 (64-byte rows, SW64 swizzle), 4-stage cp.async pipeline.
// One A-split live at a time (reg-pressure control); 6 split products.
// ---------------------------------------------------------------------------
#define ATILE(MF)   ((MF) * 2048)
#define BTILE(NF)   ((NF) * 2048)
#define STAGE(MF,NF) (3 * (ATILE(MF) + BTILE(NF)))
#define SMEM_OF(MF,NF) (4 * STAGE(MF,NF) + 1024)

template<int MF, int NF>
__device__ __forceinline__ void load_st(uint32_t st, int tid,
                                        const bf16* const* srcs, int koff) {
    // A splits: 3 x (MF*32 rows x 4 16B-units)
#pragma unroll
    for (int i = 0; i < 3 * MF / 2; i++) {
        int g = i * 256 + tid;
        int tI = g / (MF * 128);
        int w = g % (MF * 128);
        int row = w >> 2, c = w & 3;
        cp16(st + tI * ATILE(MF) + SWZ64(row * 64 + c * 16),
             srcs[tI] + (size_t)row * 512 + koff + c * 8);
    }
    // B splits: 3 x (NF*32 rows x 4 16B-units)
#pragma unroll
    for (int i = 0; i < 3 * NF / 2; i++) {
        int g = i * 256 + tid;
        int tI = g / (NF * 128);
        int w = g % (NF * 128);
        int row = w >> 2, c = w & 3;
        cp16(st + 3 * ATILE(MF) + tI * BTILE(NF) + SWZ64(row * 64 + c * 16),
             srcs[3 + tI] + (size_t)row * 512 + koff + c * 8);
    }
    asm volatile("cp.async.commit_group;" ::: "memory");
}

template<int MF, int NF>
__device__ __forceinline__ void mainloop_t(uint32_t smem, int tid,
                                           const bf16* const* srcs,
                                           float C[MF][NF][4]) {
    const int STG = STAGE(MF, NF);
    const int l = tid & 31, wid = tid >> 5;
    const int wm = wid >> 2, wn = wid & 3;
    const int a_row = l & 15;
    const int a_cb  = (l >> 4) << 4;
    const int b_row = (((l >> 4) & 1) << 3) + (l & 7);
    const int b_cb  = ((l >> 3) & 1) << 4;

    load_st<MF, NF>(smem + 0 * STG, tid, srcs, 0);
    load_st<MF, NF>(smem + 1 * STG, tid, srcs, 32);
    load_st<MF, NF>(smem + 2 * STG, tid, srcs, 64);

#pragma unroll 1
    for (int ch = 0; ch < 16; ch++) {
        uint32_t cur = smem + (ch & 3) * STG;
        if (ch + 3 < 16) {
            load_st<MF, NF>(smem + ((ch + 3) & 3) * STG, tid, srcs, (ch + 3) * 32);
            asm volatile("cp.async.wait_group 3;" ::: "memory");   // stage ch ready
        } else if (ch == 13) {
            asm volatile("cp.async.wait_group 2;" ::: "memory");
        } else if (ch == 14) {
            asm volatile("cp.async.wait_group 1;" ::: "memory");
        } else {
            asm volatile("cp.async.wait_group 0;" ::: "memory");
        }
        __syncthreads();

#pragma unroll
        for (int ks = 0; ks < 2; ks++) {
            uint32_t B[3][NF][2];
#pragma unroll
            for (int s = 0; s < 3; s++)
#pragma unroll
                for (int nh = 0; nh < NF / 2; nh++) {
                    uint32_t ad = cur + 3 * ATILE(MF) + s * BTILE(NF) +
                        SWZ64((wn * (NF * 8) + nh * 16 + b_row) * 64 + ks * 32 + b_cb);
                    uint32_t r0, r1, r2, r3;
                    ldsm4(r0, r1, r2, r3, ad);
                    B[s][nh * 2][0] = r0; B[s][nh * 2][1] = r1;
                    B[s][nh * 2 + 1][0] = r2; B[s][nh * 2 + 1][1] = r3;
                }
#pragma unroll
            for (int sa = 0; sa < 3; sa++) {
                uint32_t A[MF][4];
#pragma unroll
                for (int mf = 0; mf < MF; mf++) {
                    uint32_t ad = cur + sa * ATILE(MF) +
                        SWZ64((wm * (MF * 16) + mf * 16 + a_row) * 64 + ks * 32 + a_cb);
                    ldsm4(A[mf][0], A[mf][1], A[mf][2], A[mf][3], ad);
                }
#pragma unroll
                for (int sb = 0; sb < 3 - sa; sb++)
#pragma unroll
                    for (int mf = 0; mf < MF; mf++)
#pragma unroll
                        for (int nf = 0; nf < NF; nf++)
                            mma_bf16(C[mf][nf], A[mf], B[sb][nf]);
            }
        }
        __syncthreads();   // protect stage (ch&3) before reuse at ch+4
    }
}

// ---------------------------------------------------------------------------
// prep_E: E = emb @ W_ih^T + bias.  Tile 128x128, grid (16, 4)
// ---------------------------------------------------------------------------
__global__ __launch_bounds__(256, 1) void prep_E_kernel() {
    extern __shared__ char dsm[];
    uint32_t smem = (smem_u32(dsm) + 1023) & ~1023u;
    int tid = threadIdx.x;
    int l = tid & 31, wid = tid >> 5;
    int wm = wid >> 2, wn = wid & 3, tg = l & 3;
    int n0 = blockIdx.x * 128, m0 = blockIdx.y * 128;

    const bf16* srcs[6] = {
        g_emb[0] + (size_t)m0 * 512, g_emb[1] + (size_t)m0 * 512,
        g_emb[2] + (size_t)m0 * 512,
        g_Wih[0] + (size_t)n0 * 512, g_Wih[1] + (size_t)n0 * 512,
        g_Wih[2] + (size_t)n0 * 512};

    float C[4][4][4] = {};
    mainloop_t<4, 4>(smem, tid, srcs, C);

#pragma unroll
    for (int mf = 0; mf < 4; mf++)
#pragma unroll
        for (int nf = 0; nf < 4; nf++) {
            int n = n0 + wn * 32 + nf * 8 + tg * 2;
#pragma unroll
            for (int rh = 0; rh < 2; rh++) {
                int m = m0 + wm * 64 + mf * 16 + (l >> 2) + rh * 8;
                float2 v = make_float2(C[mf][nf][rh * 2 + 0] + g_bias[n],
                                       C[mf][nf][rh * 2 + 1] + g_bias[n + 1]);
                *(float2*)&g_E[(size_t)m * G4H + n] = v;
            }
        }
}

// ---------------------------------------------------------------------------
// Gates: gates = h @ W_hh^T (+ E[token]) -> fused LSTM cell.
// Tile 128x128, grid (16, 8).  Token comes from g_amax[rd^1] (prev logits);
// clears g_amax[rd] for this step's logits.
// ---------------------------------------------------------------------------
__global__ __launch_bounds__(256, 1) void gates_tc(int rd) {
    extern __shared__ char dsm[];
    uint32_t smem = (smem_u32(dsm) + 1023) & ~1023u;
    int tid = threadIdx.x;
    int l = tid & 31, wid = tid >> 5;
    int wm = wid >> 2, wn = wid & 3, tg = l & 3;
    int n0 = blockIdx.x * 128, m0 = blockIdx.y * 128;
    int wr = rd ^ 1;

    if (tid < 128) g_amax[rd][m0 + tid] = 0ull;   // clear before this step's logits

    const bf16* srcs[6] = {
        g_hs[rd][0] + (size_t)m0 * 512, g_hs[rd][1] + (size_t)m0 * 512,
        g_hs[rd][2] + (size_t)m0 * 512,
        g_Whh[0] + (size_t)n0 * 512, g_Whh[1] + (size_t)n0 * 512,
        g_Whh[2] + (size_t)n0 * 512};

    float C[4][4][4] = {};
    mainloop_t<4, 4>(smem, tid, srcs, C);

    // Epilogue: even-tg lane holds (i,f) pre-acts; partner (tg^1) holds (g,o).
#pragma unroll
    for (int mf = 0; mf < 4; mf++)
#pragma unroll
        for (int rh = 0; rh < 2; rh++) {
            int m = m0 + wm * 64 + mf * 16 + (l >> 2) + rh * 8;
            int tok = 511 - (int)(g_amax[wr][m] & 0x3ffull);
            const float* Erow = g_E + (size_t)tok * G4H;
#pragma unroll
            for (int nf = 0; nf < 4; nf++) {
                float own0 = C[mf][nf][rh * 2 + 0];
                float own1 = C[mf][nf][rh * 2 + 1];
                float p0 = __shfl_xor_sync(0xffffffffu, own0, 1);
                float p1 = __shfl_xor_sync(0xffffffffu, own1, 1);
                if (!(tg & 1)) {
                    int n = n0 + wn * 32 + nf * 8 + tg * 2;   // = 4*j
                    int j = n >> 2;
                    float4 e = *(const float4*)&Erow[n];
                    float gi = own0 + e.x;
                    float gf = own1 + e.y;
                    float gg = p0 + e.z;
                    float go = p1 + e.w;
                    float is = 1.f / (1.f + expf(-gi));
                    float fs = 1.f / (1.f + expf(-gf));
                    float os = 1.f / (1.f + expf(-go));
                    size_t hx = (size_t)m * HID + j;
                    float cn = fs * g_c[hx] + is * tanhf(gg);
                    g_c[hx] = cn;
                    float hn = os * tanhf(cn);
                    split3(hn, g_hs[wr][0][hx], g_hs[wr][1][hx], g_hs[wr][2][hx]);
                }
            }
        }
}

// ---------------------------------------------------------------------------
// Logits: out = h @ W_out^T + b_out, fused per-row argmax via atomicMax.
// Tile 64x64, grid (8, 16).  ph = h buffer to read; ab = amax buffer to write.
// ---------------------------------------------------------------------------
__global__ __launch_bounds__(256, 1) void logits_tc(int ph, int ab,
                                                    const float* __restrict__ bo,
                                                    float* __restrict__ out_t) {
    extern __shared__ char dsm[];
    uint32_t smem = (smem_u32(dsm) + 1023) & ~1023u;
    int tid = threadIdx.x;
    int l = tid & 31, wid = tid >> 5;
    int wm = wid >> 2, wn = wid & 3, tg = l & 3;
    int n0 = blockIdx.x * 64, m0 = blockIdx.y * 64;

    const bf16* srcs[6] = {
        g_hs[ph][0] + (size_t)m0 * 512, g_hs[ph][1] + (size_t)m0 * 512,
        g_hs[ph][2] + (size_t)m0 * 512,
        g_Wo[0] + (size_t)n0 * 512, g_Wo[1] + (size_t)n0 * 512,
        g_Wo[2] + (size_t)n0 * 512};

    float C[2][2][4] = {};
    mainloop_t<2, 2>(smem, tid, srcs, C);

#pragma unroll
    for (int mf = 0; mf < 2; mf++)
#pragma unroll
        for (int rh = 0; rh < 2; rh++) {
            int m = m0 + wm * 32 + mf * 16 + (l >> 2) + rh * 8;
            u64 best = 0ull;
#pragma unroll
            for (int nf = 0; nf < 2; nf++) {
                int n = n0 + wn * 16 + nf * 8 + tg * 2;
                float v0 = C[mf][nf][rh * 2 + 0] + bo[n];
                float v1 = C[mf][nf][rh * 2 + 1] + bo[n + 1];
                *(float2*)&out_t[(size_t)m * VOCAB + n] = make_float2(v0, v1);
                u64 k0 = amax_key(v0, n), k1 = amax_key(v1, n + 1);
                if (k0 > best) best = k0;
                if (k1 > best) best = k1;
            }
            u64 o1 = __shfl_xor_sync(0xffffffffu, best, 1);
            if (o1 > best) best = o1;
            u64 o2 = __shfl_xor_sync(0xffffffffu, best, 2);
            if (o2 > best) best = o2;
            if (tg == 0) atomicMax(&g_amax[ab][m], best);
        }
}

// ---------------------------------------------------------------------------
// Launch
// ---------------------------------------------------------------------------
extern "C" void kernel_launch(void* const* d_in, const int* in_sizes, int n_in,
                              void* d_out, int out_size) {
    const float* enc_h = (const float*)d_in[2];
    const float* enc_c = (const float*)d_in[3];
    const float* emb   = (const float*)d_in[4];
    const float* W_ih  = (const float*)d_in[5];
    const float* W_hh  = (const float*)d_in[6];
    const float* b_ih  = (const float*)d_in[7];
    const float* b_hh  = (const float*)d_in[8];
    const float* W_out = (const float*)d_in[9];
    const float* b_out = (const float*)d_in[10];
    float* out = (float*)d_out;

    const int GSM = SMEM_OF(4, 4);   // 4*49152 + 1024 = 197632
    const int LSM = SMEM_OF(2, 2);   // 4*24576 + 1024 =  99328
    cudaFuncSetAttribute(prep_E_kernel, cudaFuncAttributeMaxDynamicSharedMemorySize, GSM);
    cudaFuncSetAttribute(gates_tc, cudaFuncAttributeMaxDynamicSharedMemorySize, GSM);
    cudaFuncSetAttribute(logits_tc, cudaFuncAttributeMaxDynamicSharedMemorySize, LSM);

    prep_gates<<<(G4H * HID) / 256, 256>>>(W_ih, W_hh, b_ih, b_hh);
    prep_out<<<(VOCAB * HID) / 256, 256>>>(W_out, emb);
    init_state_tc<<<(BATCH * HID) / 256, 256>>>(enc_h, enc_c);
    prep_E_kernel<<<dim3(16, 4), 256, GSM>>>();

    for (int t = 0; t < T_STEPS; t++) {
        int rd = t & 1;
        gates_tc<<<dim3(16, 8), 256, GSM>>>(rd);
        float* logits_t = out + (size_t)t * BATCH * VOCAB;
        logits_tc<<<dim3(8, 16), 256, LSM>>>(rd ^ 1, rd, b_out, logits_t);
    }
}

// round 11
// speedup vs baseline: 1.1393x; 1.0894x over previous
#include <cuda_runtime.h>
#include <cuda_bf16.h>
#include <math.h>
#include <stdint.h>

#define T_STEPS 64
#define BATCH   1024
#define HID     512
#define VOCAB   512
#define G4H     2048

typedef __nv_bfloat16 bf16;
typedef unsigned long long u64;

// ---------------------------------------------------------------------------
// Device-global scratch (allocation-free)
// ---------------------------------------------------------------------------
__device__ float g_c[BATCH * HID];            // cell state fp32
__device__ bf16  g_hs[2][3][BATCH * HID];     // h 3-way splits, ping-pong
__device__ bf16  g_Wih[3][G4H * HID];         // gate-interleaved W_ih splits
__device__ bf16  g_Whh[3][G4H * HID];         // gate-interleaved W_hh splits
__device__ bf16  g_Wo[3][VOCAB * HID];        // W_out splits
__device__ bf16  g_emb[3][VOCAB * HID];       // embedding splits
__device__ float g_bias[G4H];                 // gate-interleaved b_ih+b_hh
__device__ float g_E[VOCAB * G4H];            // emb @ W_ih^T + bias (fp32)
__device__ u64   g_amax[2][BATCH];            // packed (mapped logit, 511-col)

// ---------------------------------------------------------------------------
// Helpers
// ---------------------------------------------------------------------------
__device__ __forceinline__ uint32_t smem_u32(const void* p) {
    uint32_t a;
    asm("{ .reg .u64 t; cvta.to.shared.u64 t, %1; cvt.u32.u64 %0, t; }"
        : "=r"(a) : "l"(p));
    return a;
}

#define SWZ(x) ((x) ^ (((x) >> 3) & 0x70))

__device__ __forceinline__ void cp16(uint32_t dst, const void* src) {
    asm volatile("cp.async.cg.shared.global [%0], [%1], 16;" :: "r"(dst), "l"(src));
}

__device__ __forceinline__ void ldsm4(uint32_t& r0, uint32_t& r1,
                                      uint32_t& r2, uint32_t& r3, uint32_t addr) {
    asm volatile("ldmatrix.sync.aligned.m8n8.x4.shared.b16 {%0,%1,%2,%3}, [%4];"
                 : "=r"(r0), "=r"(r1), "=r"(r2), "=r"(r3) : "r"(addr));
}

__device__ __forceinline__ void mma_bf16(float c[4], const uint32_t a[4],
                                         const uint32_t b[2]) {
    asm volatile(
        "mma.sync.aligned.m16n8k16.row.col.f32.bf16.bf16.f32 "
        "{%0,%1,%2,%3}, {%4,%5,%6,%7}, {%8,%9}, {%0,%1,%2,%3};"
        : "+f"(c[0]), "+f"(c[1]), "+f"(c[2]), "+f"(c[3])
        : "r"(a[0]), "r"(a[1]), "r"(a[2]), "r"(a[3]), "r"(b[0]), "r"(b[1]));
}

// Exact 3-way bf16 split
__device__ __forceinline__ void split3(float v, bf16& s0, bf16& s1, bf16& s2) {
    s0 = __float2bfloat16(v);
    float r = v - __bfloat162float(s0);
    s1 = __float2bfloat16(r);
    float r2 = r - __bfloat162float(s1);
    s2 = __float2bfloat16(r2);
}

// Monotone float->u32 map; key packs (value, 511-col) for first-max argmax
__device__ __forceinline__ u64 amax_key(float v, int col) {
    uint32_t u = __float_as_uint(v);
    uint32_t mu = (u & 0x80000000u) ? ~u : (u | 0x80000000u);
    return ((u64)mu << 32) | (uint32_t)(511 - col);
}

// ---------------------------------------------------------------------------
// Prep kernels
// ---------------------------------------------------------------------------
__global__ void prep_gates(const float* __restrict__ Wih, const float* __restrict__ Whh,
                           const float* __restrict__ bih, const float* __restrict__ bhh) {
    int idx = blockIdx.x * blockDim.x + threadIdx.x;    // [0, G4H*HID)
    int n = idx >> 9;
    int k = idx & 511;
    int orig = ((n & 3) << 9) + (n >> 2);               // interleave i,f,g,o per j
    split3(Wih[(size_t)orig * 512 + k], g_Wih[0][idx], g_Wih[1][idx], g_Wih[2][idx]);
    split3(Whh[(size_t)orig * 512 + k], g_Whh[0][idx], g_Whh[1][idx], g_Whh[2][idx]);
    if (k == 0) g_bias[n] = bih[orig] + bhh[orig];
}

__global__ void prep_out(const float* __restrict__ Wout, const float* __restrict__ emb) {
    int idx = blockIdx.x * blockDim.x + threadIdx.x;    // [0, VOCAB*HID)
    split3(Wout[idx], g_Wo[0][idx], g_Wo[1][idx], g_Wo[2][idx]);
    split3(emb[idx], g_emb[0][idx], g_emb[1][idx], g_emb[2][idx]);
}

__global__ void init_state_tc(const float* __restrict__ ench,
                              const float* __restrict__ encc) {
    int idx = blockIdx.x * blockDim.x + threadIdx.x;    // [0, BATCH*HID)
    g_c[idx] = encc[idx];
    split3(ench[idx], g_hs[0][0][idx], g_hs[0][1][idx], g_hs[0][2][idx]);
    if ((idx & 511) == 0) g_amax[1][idx >> 9] = 511ull;  // decodes to SOS token 0
}

// ---------------------------------------------------------------------------
// 128x128 main loop (K=512 in 8 chunks of 64), 256 threads, 8 warps (2Mx4N)
// Warp tile 64x32.  smem: double buffer of 6 tiles x 16KB (3 A splits, 3 B).
// One A-split live at a time.  (Round-7-proven configuration.)
// ---------------------------------------------------------------------------
#define TILE128   16384
#define BUF128    (6 * TILE128)        // 98304
#define SMEM128   (2 * BUF128 + 1024)

__device__ __forceinline__ void load128(uint32_t bufb, int tid,
                                        const bf16* const srcs[6], int koff) {
#pragma unroll
    for (int i = 0; i < 24; i++) {
        int u = tid + i * 256;
        int row = (u >> 3) & 127;
        int cb = u & 7;
        cp16(bufb + ((i >> 2) << 14) + SWZ(row * 128 + cb * 16),
             srcs[i >> 2] + (size_t)row * 512 + koff + cb * 8);
    }
    asm volatile("cp.async.commit_group;" ::: "memory");
}

__device__ __forceinline__ void mainloop128(uint32_t smem, int tid,
                                            const bf16* const srcs[6],
                                            float C[4][4][4]) {
    const int l = tid & 31, wid = tid >> 5;
    const int wm = wid >> 2, wn = wid & 3;

    const int a_row = l & 15;
    const int a_cb  = (l >> 4) << 4;
    const int b_row = (((l >> 4) & 1) << 3) + (l & 7);
    const int b_cb  = ((l >> 3) & 1) << 4;

    load128(smem, tid, srcs, 0);

#pragma unroll 1
    for (int ch = 0; ch < 8; ch++) {
        uint32_t cur = smem + (ch & 1) * BUF128;
        if (ch < 7) {
            load128(smem + ((ch + 1) & 1) * BUF128, tid, srcs, (ch + 1) * 64);
            asm volatile("cp.async.wait_group 1;" ::: "memory");
        } else {
            asm volatile("cp.async.wait_group 0;" ::: "memory");
        }
        __syncthreads();

#pragma unroll
        for (int ks = 0; ks < 4; ks++) {
            uint32_t B[3][4][2];
#pragma unroll
            for (int s = 0; s < 3; s++) {
#pragma unroll
                for (int nh = 0; nh < 2; nh++) {
                    uint32_t ad = cur + 3 * TILE128 + (s << 14) +
                        SWZ((wn * 32 + nh * 16 + b_row) * 128 + ks * 32 + b_cb);
                    uint32_t r0, r1, r2, r3;
                    ldsm4(r0, r1, r2, r3, ad);
                    B[s][nh * 2][0] = r0; B[s][nh * 2][1] = r1;
                    B[s][nh * 2 + 1][0] = r2; B[s][nh * 2 + 1][1] = r3;
                }
            }
#pragma unroll
            for (int sa = 0; sa < 3; sa++) {
                uint32_t A[4][4];
#pragma unroll
                for (int mf = 0; mf < 4; mf++) {
                    uint32_t ad = cur + (sa << 14) +
                        SWZ((wm * 64 + mf * 16 + a_row) * 128 + ks * 32 + a_cb);
                    ldsm4(A[mf][0], A[mf][1], A[mf][2], A[mf][3], ad);
                }
#pragma unroll
                for (int sb = 0; sb < 3 - sa; sb++) {
#pragma unroll
                    for (int mf = 0; mf < 4; mf++)
#pragma unroll
                        for (int nf = 0; nf < 4; nf++)
                            mma_bf16(C[mf][nf], A[mf], B[sb][nf]);
                }
            }
        }
        __syncthreads();
    }
}

// ---------------------------------------------------------------------------
// prep_E: E = emb @ W_ih^T + bias  (M=512, N=2048, K=512), grid (16, 4)
// ---------------------------------------------------------------------------
__global__ __launch_bounds__(256, 1) void prep_E_kernel() {
    extern __shared__ char dsm[];
    uint32_t smem = (smem_u32(dsm) + 1023) & ~1023u;
    int tid = threadIdx.x;
    int l = tid & 31, wid = tid >> 5;
    int wm = wid >> 2, wn = wid & 3, tg = l & 3;
    int n0 = blockIdx.x * 128, m0 = blockIdx.y * 128;

    const bf16* srcs[6] = {
        g_emb[0] + (size_t)m0 * 512, g_emb[1] + (size_t)m0 * 512,
        g_emb[2] + (size_t)m0 * 512,
        g_Wih[0] + (size_t)n0 * 512, g_Wih[1] + (size_t)n0 * 512,
        g_Wih[2] + (size_t)n0 * 512};

    float C[4][4][4] = {};
    mainloop128(smem, tid, srcs, C);

#pragma unroll
    for (int mf = 0; mf < 4; mf++)
#pragma unroll
        for (int nf = 0; nf < 4; nf++) {
            int n = n0 + wn * 32 + nf * 8 + tg * 2;
#pragma unroll
            for (int rh = 0; rh < 2; rh++) {
                int m = m0 + wm * 64 + mf * 16 + (l >> 2) + rh * 8;
                float2 v = make_float2(C[mf][nf][rh * 2 + 0] + g_bias[n],
                                       C[mf][nf][rh * 2 + 1] + g_bias[n + 1]);
                *(float2*)&g_E[(size_t)m * G4H + n] = v;
            }
        }
}

// ---------------------------------------------------------------------------
// Gates: gates = h @ W_hh^T (+ E[token]) -> fused LSTM cell.
// Tile 128x128, grid (16, 8).  Token from g_amax[rd^1], prefetched at start;
// clears g_amax[rd] for this step's logits.
// ---------------------------------------------------------------------------
__global__ __launch_bounds__(256, 1) void gates_tc(int rd) {
    extern __shared__ char dsm[];
    uint32_t smem = (smem_u32(dsm) + 1023) & ~1023u;
    int tid = threadIdx.x;
    int l = tid & 31, wid = tid >> 5;
    int wm = wid >> 2, wn = wid & 3, tg = l & 3;
    int n0 = blockIdx.x * 128, m0 = blockIdx.y * 128;
    int wr = rd ^ 1;

    // Prefetch previous-step argmax keys for this thread's 8 m-rows (hides the
    // dependent amax->E LDG chain behind the mainloop).
    int tok8[4][2];
#pragma unroll
    for (int mf = 0; mf < 4; mf++)
#pragma unroll
        for (int rh = 0; rh < 2; rh++) {
            int m = m0 + wm * 64 + mf * 16 + (l >> 2) + rh * 8;
            tok8[mf][rh] = 511 - (int)(g_amax[wr][m] & 0x3ffull);
        }

    if (tid < 128) g_amax[rd][m0 + tid] = 0ull;   // clear for this step's logits

    const bf16* srcs[6] = {
        g_hs[rd][0] + (size_t)m0 * 512, g_hs[rd][1] + (size_t)m0 * 512,
        g_hs[rd][2] + (size_t)m0 * 512,
        g_Whh[0] + (size_t)n0 * 512, g_Whh[1] + (size_t)n0 * 512,
        g_Whh[2] + (size_t)n0 * 512};

    float C[4][4][4] = {};
    mainloop128(smem, tid, srcs, C);

    // Epilogue: even-tg lane holds (i,f) pre-acts; partner (tg^1) holds (g,o).
#pragma unroll
    for (int mf = 0; mf < 4; mf++)
#pragma unroll
        for (int rh = 0; rh < 2; rh++) {
            int m = m0 + wm * 64 + mf * 16 + (l >> 2) + rh * 8;
            const float* Erow = g_E + (size_t)tok8[mf][rh] * G4H;
#pragma unroll
            for (int nf = 0; nf < 4; nf++) {
                float own0 = C[mf][nf][rh * 2 + 0];
                float own1 = C[mf][nf][rh * 2 + 1];
                float p0 = __shfl_xor_sync(0xffffffffu, own0, 1);
                float p1 = __shfl_xor_sync(0xffffffffu, own1, 1);
                if (!(tg & 1)) {
                    int n = n0 + wn * 32 + nf * 8 + tg * 2;   // = 4*j
                    int j = n >> 2;
                    float4 e = *(const float4*)&Erow[n];
                    float gi = own0 + e.x;
                    float gf = own1 + e.y;
                    float gg = p0 + e.z;
                    float go = p1 + e.w;
                    float is = 1.f / (1.f + expf(-gi));
                    float fs = 1.f / (1.f + expf(-gf));
                    float os = 1.f / (1.f + expf(-go));
                    size_t hx = (size_t)m * HID + j;
                    float cn = fs * g_c[hx] + is * tanhf(gg);
                    g_c[hx] = cn;
                    float hn = os * tanhf(cn);
                    split3(hn, g_hs[wr][0][hx], g_hs[wr][1][hx], g_hs[wr][2][hx]);
                }
            }
        }
}

// ---------------------------------------------------------------------------
// Logits: out = h @ W_out^T + b_out, fused per-row argmax via atomicMax.
// Tile 64x64, grid (8, 16), 256 threads, warp tile 32x16 (2Mx4N).
// ---------------------------------------------------------------------------
#define TILE64   8192
#define BUF64    (6 * TILE64)          // 49152
#define SMEM64   (2 * BUF64 + 1024)

__device__ __forceinline__ void load64(uint32_t bufb, int tid,
                                       const bf16* const srcs[6], int koff) {
#pragma unroll
    for (int i = 0; i < 12; i++) {
        int u = tid + i * 256;
        int row = (u >> 3) & 63;
        int cb = u & 7;
        cp16(bufb + ((i >> 1) << 13) + SWZ(row * 128 + cb * 16),
             srcs[i >> 1] + (size_t)row * 512 + koff + cb * 8);
    }
    asm volatile("cp.async.commit_group;" ::: "memory");
}

__global__ __launch_bounds__(256, 1) void logits_tc(int ph, int ab,
                                                    const float* __restrict__ bo,
                                                    float* __restrict__ out_t) {
    extern __shared__ char dsm[];
    uint32_t smem = (smem_u32(dsm) + 1023) & ~1023u;
    int tid = threadIdx.x;
    int l = tid & 31, wid = tid >> 5;
    int wm = wid >> 2, wn = wid & 3, tg = l & 3;
    int n0 = blockIdx.x * 64, m0 = blockIdx.y * 64;

    const bf16* srcs[6] = {
        g_hs[ph][0] + (size_t)m0 * 512, g_hs[ph][1] + (size_t)m0 * 512,
        g_hs[ph][2] + (size_t)m0 * 512,
        g_Wo[0] + (size_t)n0 * 512, g_Wo[1] + (size_t)n0 * 512,
        g_Wo[2] + (size_t)n0 * 512};

    const int a_row = l & 15;
    const int a_cb  = (l >> 4) << 4;
    const int b_row = (((l >> 4) & 1) << 3) + (l & 7);
    const int b_cb  = ((l >> 3) & 1) << 4;

    float C[2][2][4] = {};

    load64(smem, tid, srcs, 0);
#pragma unroll 1
    for (int ch = 0; ch < 8; ch++) {
        uint32_t cur = smem + (ch & 1) * BUF64;
        if (ch < 7) {
            load64(smem + ((ch + 1) & 1) * BUF64, tid, srcs, (ch + 1) * 64);
            asm volatile("cp.async.wait_group 1;" ::: "memory");
        } else {
            asm volatile("cp.async.wait_group 0;" ::: "memory");
        }
        __syncthreads();

#pragma unroll
        for (int ks = 0; ks < 4; ks++) {
            uint32_t B[3][2][2];
#pragma unroll
            for (int s = 0; s < 3; s++) {
                uint32_t ad = cur + 3 * TILE64 + (s << 13) +
                    SWZ((wn * 16 + b_row) * 128 + ks * 32 + b_cb);
                uint32_t r0, r1, r2, r3;
                ldsm4(r0, r1, r2, r3, ad);
                B[s][0][0] = r0; B[s][0][1] = r1;
                B[s][1][0] = r2; B[s][1][1] = r3;
            }
#pragma unroll
            for (int sa = 0; sa < 3; sa++) {
                uint32_t A[2][4];
#pragma unroll
                for (int mf = 0; mf < 2; mf++) {
                    uint32_t ad = cur + (sa << 13) +
                        SWZ((wm * 32 + mf * 16 + a_row) * 128 + ks * 32 + a_cb);
                    ldsm4(A[mf][0], A[mf][1], A[mf][2], A[mf][3], ad);
                }
#pragma unroll
                for (int sb = 0; sb < 3 - sa; sb++) {
#pragma unroll
                    for (int mf = 0; mf < 2; mf++)
#pragma unroll
                        for (int nf = 0; nf < 2; nf++)
                            mma_bf16(C[mf][nf], A[mf], B[sb][nf]);
                }
            }
        }
        __syncthreads();
    }

#pragma unroll
    for (int mf = 0; mf < 2; mf++)
#pragma unroll
        for (int rh = 0; rh < 2; rh++) {
            int m = m0 + wm * 32 + mf * 16 + (l >> 2) + rh * 8;
            u64 best = 0ull;
#pragma unroll
            for (int nf = 0; nf < 2; nf++) {
                int n = n0 + wn * 16 + nf * 8 + tg * 2;
                float v0 = C[mf][nf][rh * 2 + 0] + bo[n];
                float v1 = C[mf][nf][rh * 2 + 1] + bo[n + 1];
                *(float2*)&out_t[(size_t)m * VOCAB + n] = make_float2(v0, v1);
                u64 k0 = amax_key(v0, n), k1 = amax_key(v1, n + 1);
                if (k0 > best) best = k0;
                if (k1 > best) best = k1;
            }
            u64 o1 = __shfl_xor_sync(0xffffffffu, best, 1);
            if (o1 > best) best = o1;
            u64 o2 = __shfl_xor_sync(0xffffffffu, best, 2);
            if (o2 > best) best = o2;
            if (tg == 0) atomicMax(&g_amax[ab][m], best);
        }
}

// ---------------------------------------------------------------------------
// Launch
// ---------------------------------------------------------------------------
extern "C" void kernel_launch(void* const* d_in, const int* in_sizes, int n_in,
                              void* d_out, int out_size) {
    const float* enc_h = (const float*)d_in[2];
    const float* enc_c = (const float*)d_in[3];
    const float* emb   = (const float*)d_in[4];
    const float* W_ih  = (const float*)d_in[5];
    const float* W_hh  = (const float*)d_in[6];
    const float* b_ih  = (const float*)d_in[7];
    const float* b_hh  = (const float*)d_in[8];
    const float* W_out = (const float*)d_in[9];
    const float* b_out = (const float*)d_in[10];
    float* out = (float*)d_out;

    cudaFuncSetAttribute(prep_E_kernel, cudaFuncAttributeMaxDynamicSharedMemorySize, SMEM128);
    cudaFuncSetAttribute(gates_tc, cudaFuncAttributeMaxDynamicSharedMemorySize, SMEM128);
    cudaFuncSetAttribute(logits_tc, cudaFuncAttributeMaxDynamicSharedMemorySize, SMEM64);

    prep_gates<<<(G4H * HID) / 256, 256>>>(W_ih, W_hh, b_ih, b_hh);
    prep_out<<<(VOCAB * HID) / 256, 256>>>(W_out, emb);
    init_state_tc<<<(BATCH * HID) / 256, 256>>>(enc_h, enc_c);
    prep_E_kernel<<<dim3(16, 4), 256, SMEM128>>>();

    for (int t = 0; t < T_STEPS; t++) {
        int rd = t & 1;
        gates_tc<<<dim3(16, 8), 256, SMEM128>>>(rd);
        float* logits_t = out + (size_t)t * BATCH * VOCAB;
        logits_tc<<<dim3(8, 16), 256, SMEM64>>>(rd ^ 1, rd, b_out, logits_t);
    }
}

// round 12
// speedup vs baseline: 1.6305x; 1.4312x over previous
#include <cuda_runtime.h>
#include <cuda_fp16.h>
#include <math.h>
#include <stdint.h>

#define T_STEPS 64
#define BATCH   1024
#define HID     512
#define VOCAB   512
#define G4H     2048

typedef unsigned long long u64;

// ---------------------------------------------------------------------------
// Device-global scratch (allocation-free)
// A-side operands (h, emb) pre-scaled by 16; B-side weights by 32.
// GEMM accumulators therefore carry 512x; epilogues multiply by 1/512.
// ---------------------------------------------------------------------------
__device__ float  g_c[BATCH * HID];            // cell state fp32
__device__ __half g_hs[2][2][BATCH * HID];     // 16*h 2-way fp16 splits, ping-pong
__device__ __half g_Wih[2][G4H * HID];         // 32*W_ih splits (gate-interleaved)
__device__ __half g_Whh[2][G4H * HID];         // 32*W_hh splits (gate-interleaved)
__device__ __half g_Wo[2][VOCAB * HID];        // 32*W_out splits
__device__ __half g_emb[2][VOCAB * HID];       // 16*embedding splits
__device__ float  g_bias[G4H];                 // gate-interleaved b_ih+b_hh
__device__ float  g_E[VOCAB * G4H];            // emb @ W_ih^T + bias (fp32, true scale)
__device__ u64    g_amax[2][BATCH];            // packed (mapped logit, 511-col)

#define INV512 (1.0f / 512.0f)

// ---------------------------------------------------------------------------
// Helpers
// ---------------------------------------------------------------------------
__device__ __forceinline__ uint32_t smem_u32(const void* p) {
    uint32_t a;
    asm("{ .reg .u64 t; cvta.to.shared.u64 t, %1; cvt.u32.u64 %0, t; }"
        : "=r"(a) : "l"(p));
    return a;
}

#define SWZ(x) ((x) ^ (((x) >> 3) & 0x70))

__device__ __forceinline__ void cp16(uint32_t dst, const void* src) {
    asm volatile("cp.async.cg.shared.global [%0], [%1], 16;" :: "r"(dst), "l"(src));
}

__device__ __forceinline__ void ldsm4(uint32_t& r0, uint32_t& r1,
                                      uint32_t& r2, uint32_t& r3, uint32_t addr) {
    asm volatile("ldmatrix.sync.aligned.m8n8.x4.shared.b16 {%0,%1,%2,%3}, [%4];"
                 : "=r"(r0), "=r"(r1), "=r"(r2), "=r"(r3) : "r"(addr));
}

__device__ __forceinline__ void mma_f16(float c[4], const uint32_t a[4],
                                        const uint32_t b[2]) {
    asm volatile(
        "mma.sync.aligned.m16n8k16.row.col.f32.f16.f16.f32 "
        "{%0,%1,%2,%3}, {%4,%5,%6,%7}, {%8,%9}, {%0,%1,%2,%3};"
        : "+f"(c[0]), "+f"(c[1]), "+f"(c[2]), "+f"(c[3])
        : "r"(a[0]), "r"(a[1]), "r"(a[2]), "r"(a[3]), "r"(b[0]), "r"(b[1]));
}

// Exact 2-way fp16 split of a pre-scaled value
__device__ __forceinline__ void split2(float v, __half& s0, __half& s1) {
    s0 = __float2half_rn(v);
    s1 = __float2half_rn(v - __half2float(s0));
}

// Monotone float->u32 map; key packs (value, 511-col) for first-max argmax
__device__ __forceinline__ u64 amax_key(float v, int col) {
    uint32_t u = __float_as_uint(v);
    uint32_t mu = (u & 0x80000000u) ? ~u : (u | 0x80000000u);
    return ((u64)mu << 32) | (uint32_t)(511 - col);
}

// ---------------------------------------------------------------------------
// Prep kernels
// ---------------------------------------------------------------------------
__global__ void prep_gates(const float* __restrict__ Wih, const float* __restrict__ Whh,
                           const float* __restrict__ bih, const float* __restrict__ bhh) {
    int idx = blockIdx.x * blockDim.x + threadIdx.x;    // [0, G4H*HID)
    int n = idx >> 9;
    int k = idx & 511;
    int orig = ((n & 3) << 9) + (n >> 2);               // interleave i,f,g,o per j
    split2(32.0f * Wih[(size_t)orig * 512 + k], g_Wih[0][idx], g_Wih[1][idx]);
    split2(32.0f * Whh[(size_t)orig * 512 + k], g_Whh[0][idx], g_Whh[1][idx]);
    if (k == 0) g_bias[n] = bih[orig] + bhh[orig];
}

__global__ void prep_out(const float* __restrict__ Wout, const float* __restrict__ emb) {
    int idx = blockIdx.x * blockDim.x + threadIdx.x;    // [0, VOCAB*HID)
    split2(32.0f * Wout[idx], g_Wo[0][idx], g_Wo[1][idx]);
    split2(16.0f * emb[idx], g_emb[0][idx], g_emb[1][idx]);
}

__global__ void init_state_tc(const float* __restrict__ ench,
                              const float* __restrict__ encc) {
    int idx = blockIdx.x * blockDim.x + threadIdx.x;    // [0, BATCH*HID)
    g_c[idx] = encc[idx];
    split2(16.0f * ench[idx], g_hs[0][0][idx], g_hs[0][1][idx]);
    if ((idx & 511) == 0) g_amax[1][idx >> 9] = 511ull;  // decodes to SOS token 0
}

// ---------------------------------------------------------------------------
// 128x128 main loop (K=512 in 8 chunks of 64), 256 threads, 8 warps (2Mx4N)
// Warp tile 64x32.  smem: double buffer of 4 tiles x 16KB (2 A splits, 2 B).
// Split products (0,0),(0,1),(1,0); one A-split live at a time.
// ---------------------------------------------------------------------------
#define TILE128   16384
#define BUF128    (4 * TILE128)        // 65536
#define SMEM128   (2 * BUF128 + 1024)

__device__ __forceinline__ void load128(uint32_t bufb, int tid,
                                        const __half* const srcs[4], int koff) {
#pragma unroll
    for (int i = 0; i < 16; i++) {
        int t = i >> 2;
        int u = tid + (i & 3) * 256;
        int row = u >> 3;
        int cb = u & 7;
        cp16(bufb + (t << 14) + SWZ(row * 128 + cb * 16),
             srcs[t] + (size_t)row * 512 + koff + cb * 8);
    }
    asm volatile("cp.async.commit_group;" ::: "memory");
}

__device__ __forceinline__ void mainloop128(uint32_t smem, int tid,
                                            const __half* const srcs[4],
                                            float C[4][4][4]) {
    const int l = tid & 31, wid = tid >> 5;
    const int wm = wid >> 2, wn = wid & 3;

    const int a_row = l & 15;
    const int a_cb  = (l >> 4) << 4;
    const int b_row = (((l >> 4) & 1) << 3) + (l & 7);
    const int b_cb  = ((l >> 3) & 1) << 4;

    load128(smem, tid, srcs, 0);

#pragma unroll 1
    for (int ch = 0; ch < 8; ch++) {
        uint32_t cur = smem + (ch & 1) * BUF128;
        if (ch < 7) {
            load128(smem + ((ch + 1) & 1) * BUF128, tid, srcs, (ch + 1) * 64);
            asm volatile("cp.async.wait_group 1;" ::: "memory");
        } else {
            asm volatile("cp.async.wait_group 0;" ::: "memory");
        }
        __syncthreads();

#pragma unroll
        for (int ks = 0; ks < 4; ks++) {
            uint32_t B[2][4][2];
#pragma unroll
            for (int s = 0; s < 2; s++) {
#pragma unroll
                for (int nh = 0; nh < 2; nh++) {
                    uint32_t ad = cur + ((2 + s) << 14) +
                        SWZ((wn * 32 + nh * 16 + b_row) * 128 + ks * 32 + b_cb);
                    uint32_t r0, r1, r2, r3;
                    ldsm4(r0, r1, r2, r3, ad);
                    B[s][nh * 2][0] = r0; B[s][nh * 2][1] = r1;
                    B[s][nh * 2 + 1][0] = r2; B[s][nh * 2 + 1][1] = r3;
                }
            }
#pragma unroll
            for (int sa = 0; sa < 2; sa++) {
                uint32_t A[4][4];
#pragma unroll
                for (int mf = 0; mf < 4; mf++) {
                    uint32_t ad = cur + (sa << 14) +
                        SWZ((wm * 64 + mf * 16 + a_row) * 128 + ks * 32 + a_cb);
                    ldsm4(A[mf][0], A[mf][1], A[mf][2], A[mf][3], ad);
                }
#pragma unroll
                for (int sb = 0; sb < 2 - sa; sb++) {
#pragma unroll
                    for (int mf = 0; mf < 4; mf++)
#pragma unroll
                        for (int nf = 0; nf < 4; nf++)
                            mma_f16(C[mf][nf], A[mf], B[sb][nf]);
                }
            }
        }
        __syncthreads();
    }
}

// ---------------------------------------------------------------------------
// prep_E: E = emb @ W_ih^T + bias  (M=512, N=2048, K=512), grid (16, 4)
// ---------------------------------------------------------------------------
__global__ __launch_bounds__(256, 1) void prep_E_kernel() {
    extern __shared__ char dsm[];
    uint32_t smem = (smem_u32(dsm) + 1023) & ~1023u;
    int tid = threadIdx.x;
    int l = tid & 31, wid = tid >> 5;
    int wm = wid >> 2, wn = wid & 3, tg = l & 3;
    int n0 = blockIdx.x * 128, m0 = blockIdx.y * 128;

    const __half* srcs[4] = {
        g_emb[0] + (size_t)m0 * 512, g_emb[1] + (size_t)m0 * 512,
        g_Wih[0] + (size_t)n0 * 512, g_Wih[1] + (size_t)n0 * 512};

    float C[4][4][4] = {};
    mainloop128(smem, tid, srcs, C);

#pragma unroll
    for (int mf = 0; mf < 4; mf++)
#pragma unroll
        for (int nf = 0; nf < 4; nf++) {
            int n = n0 + wn * 32 + nf * 8 + tg * 2;
#pragma unroll
            for (int rh = 0; rh < 2; rh++) {
                int m = m0 + wm * 64 + mf * 16 + (l >> 2) + rh * 8;
                float2 v = make_float2(
                    C[mf][nf][rh * 2 + 0] * INV512 + g_bias[n],
                    C[mf][nf][rh * 2 + 1] * INV512 + g_bias[n + 1]);
                *(float2*)&g_E[(size_t)m * G4H + n] = v;
            }
        }
}

// ---------------------------------------------------------------------------
// Gates: gates = h @ W_hh^T (+ E[token]) -> fused LSTM cell.
// Tile 128x128, grid (16, 8).  Token from g_amax[rd^1], prefetched at start;
// clears g_amax[rd] for this step's logits.
// ---------------------------------------------------------------------------
__global__ __launch_bounds__(256, 1) void gates_tc(int rd) {
    extern __shared__ char dsm[];
    uint32_t smem = (smem_u32(dsm) + 1023) & ~1023u;
    int tid = threadIdx.x;
    int l = tid & 31, wid = tid >> 5;
    int wm = wid >> 2, wn = wid & 3, tg = l & 3;
    int n0 = blockIdx.x * 128, m0 = blockIdx.y * 128;
    int wr = rd ^ 1;

    // Prefetch previous-step argmax keys (hides amax->E LDG chain behind GEMM)
    int tok8[4][2];
#pragma unroll
    for (int mf = 0; mf < 4; mf++)
#pragma unroll
        for (int rh = 0; rh < 2; rh++) {
            int m = m0 + wm * 64 + mf * 16 + (l >> 2) + rh * 8;
            tok8[mf][rh] = 511 - (int)(g_amax[wr][m] & 0x3ffull);
        }

    if (tid < 128) g_amax[rd][m0 + tid] = 0ull;   // clear for this step's logits

    const __half* srcs[4] = {
        g_hs[rd][0] + (size_t)m0 * 512, g_hs[rd][1] + (size_t)m0 * 512,
        g_Whh[0] + (size_t)n0 * 512, g_Whh[1] + (size_t)n0 * 512};

    float C[4][4][4] = {};
    mainloop128(smem, tid, srcs, C);

    // Epilogue: even-tg lane holds (i,f) pre-acts; partner (tg^1) holds (g,o).
#pragma unroll
    for (int mf = 0; mf < 4; mf++)
#pragma unroll
        for (int rh = 0; rh < 2; rh++) {
            int m = m0 + wm * 64 + mf * 16 + (l >> 2) + rh * 8;
            const float* Erow = g_E + (size_t)tok8[mf][rh] * G4H;
#pragma unroll
            for (int nf = 0; nf < 4; nf++) {
                float own0 = C[mf][nf][rh * 2 + 0];
                float own1 = C[mf][nf][rh * 2 + 1];
                float p0 = __shfl_xor_sync(0xffffffffu, own0, 1);
                float p1 = __shfl_xor_sync(0xffffffffu, own1, 1);
                if (!(tg & 1)) {
                    int n = n0 + wn * 32 + nf * 8 + tg * 2;   // = 4*j
                    int j = n >> 2;
                    float4 e = *(const float4*)&Erow[n];
                    float gi = own0 * INV512 + e.x;
                    float gf = own1 * INV512 + e.y;
                    float gg = p0 * INV512 + e.z;
                    float go = p1 * INV512 + e.w;
                    float is = 1.f / (1.f + expf(-gi));
                    float fs = 1.f / (1.f + expf(-gf));
                    float os = 1.f / (1.f + expf(-go));
                    size_t hx = (size_t)m * HID + j;
                    float cn = fs * g_c[hx] + is * tanhf(gg);
                    g_c[hx] = cn;
                    float hn = os * tanhf(cn);
                    split2(16.0f * hn, g_hs[wr][0][hx], g_hs[wr][1][hx]);
                }
            }
        }
}

// ---------------------------------------------------------------------------
// Logits: out = h @ W_out^T + b_out, fused per-row argmax via atomicMax.
// Tile 64x64, grid (8, 16), 256 threads, warp tile 32x16 (2Mx4N).
// ---------------------------------------------------------------------------
#define TILE64   8192
#define BUF64    (4 * TILE64)          // 32768
#define SMEM64   (2 * BUF64 + 1024)

__device__ __forceinline__ void load64(uint32_t bufb, int tid,
                                       const __half* const srcs[4], int koff) {
#pragma unroll
    for (int i = 0; i < 8; i++) {
        int t = i >> 1;
        int u = tid + (i & 1) * 256;
        int row = u >> 3;
        int cb = u & 7;
        cp16(bufb + (t << 13) + SWZ(row * 128 + cb * 16),
             srcs[t] + (size_t)row * 512 + koff + cb * 8);
    }
    asm volatile("cp.async.commit_group;" ::: "memory");
}

__global__ __launch_bounds__(256, 1) void logits_tc(int ph, int ab,
                                                    const float* __restrict__ bo,
                                                    float* __restrict__ out_t) {
    extern __shared__ char dsm[];
    uint32_t smem = (smem_u32(dsm) + 1023) & ~1023u;
    int tid = threadIdx.x;
    int l = tid & 31, wid = tid >> 5;
    int wm = wid >> 2, wn = wid & 3, tg = l & 3;
    int n0 = blockIdx.x * 64, m0 = blockIdx.y * 64;

    const __half* srcs[4] = {
        g_hs[ph][0] + (size_t)m0 * 512, g_hs[ph][1] + (size_t)m0 * 512,
        g_Wo[0] + (size_t)n0 * 512, g_Wo[1] + (size_t)n0 * 512};

    const int a_row = l & 15;
    const int a_cb  = (l >> 4) << 4;
    const int b_row = (((l >> 4) & 1) << 3) + (l & 7);
    const int b_cb  = ((l >> 3) & 1) << 4;

    float C[2][2][4] = {};

    load64(smem, tid, srcs, 0);
#pragma unroll 1
    for (int ch = 0; ch < 8; ch++) {
        uint32_t cur = smem + (ch & 1) * BUF64;
        if (ch < 7) {
            load64(smem + ((ch + 1) & 1) * BUF64, tid, srcs, (ch + 1) * 64);
            asm volatile("cp.async.wait_group 1;" ::: "memory");
        } else {
            asm volatile("cp.async.wait_group 0;" ::: "memory");
        }
        __syncthreads();

#pragma unroll
        for (int ks = 0; ks < 4; ks++) {
            uint32_t B[2][2][2];
#pragma unroll
            for (int s = 0; s < 2; s++) {
                uint32_t ad = cur + ((2 + s) << 13) +
                    SWZ((wn * 16 + b_row) * 128 + ks * 32 + b_cb);
                uint32_t r0, r1, r2, r3;
                ldsm4(r0, r1, r2, r3, ad);
                B[s][0][0] = r0; B[s][0][1] = r1;
                B[s][1][0] = r2; B[s][1][1] = r3;
            }
#pragma unroll
            for (int sa = 0; sa < 2; sa++) {
                uint32_t A[2][4];
#pragma unroll
                for (int mf = 0; mf < 2; mf++) {
                    uint32_t ad = cur + (sa << 13) +
                        SWZ((wm * 32 + mf * 16 + a_row) * 128 + ks * 32 + a_cb);
                    ldsm4(A[mf][0], A[mf][1], A[mf][2], A[mf][3], ad);
                }
#pragma unroll
                for (int sb = 0; sb < 2 - sa; sb++) {
#pragma unroll
                    for (int mf = 0; mf < 2; mf++)
#pragma unroll
                        for (int nf = 0; nf < 2; nf++)
                            mma_f16(C[mf][nf], A[mf], B[sb][nf]);
                }
            }
        }
        __syncthreads();
    }

#pragma unroll
    for (int mf = 0; mf < 2; mf++)
#pragma unroll
        for (int rh = 0; rh < 2; rh++) {
            int m = m0 + wm * 32 + mf * 16 + (l >> 2) + rh * 8;
            u64 best = 0ull;
#pragma unroll
            for (int nf = 0; nf < 2; nf++) {
                int n = n0 + wn * 16 + nf * 8 + tg * 2;
                float v0 = C[mf][nf][rh * 2 + 0] * INV512 + bo[n];
                float v1 = C[mf][nf][rh * 2 + 1] * INV512 + bo[n + 1];
                *(float2*)&out_t[(size_t)m * VOCAB + n] = make_float2(v0, v1);
                u64 k0 = amax_key(v0, n), k1 = amax_key(v1, n + 1);
                if (k0 > best) best = k0;
                if (k1 > best) best = k1;
            }
            u64 o1 = __shfl_xor_sync(0xffffffffu, best, 1);
            if (o1 > best) best = o1;
            u64 o2 = __shfl_xor_sync(0xffffffffu, best, 2);
            if (o2 > best) best = o2;
            if (tg == 0) atomicMax(&g_amax[ab][m], best);
        }
}

// ---------------------------------------------------------------------------
// Launch
// ---------------------------------------------------------------------------
extern "C" void kernel_launch(void* const* d_in, const int* in_sizes, int n_in,
                              void* d_out, int out_size) {
    const float* enc_h = (const float*)d_in[2];
    const float* enc_c = (const float*)d_in[3];
    const float* emb   = (const float*)d_in[4];
    const float* W_ih  = (const float*)d_in[5];
    const float* W_hh  = (const float*)d_in[6];
    const float* b_ih  = (const float*)d_in[7];
    const float* b_hh  = (const float*)d_in[8];
    const float* W_out = (const float*)d_in[9];
    const float* b_out = (const float*)d_in[10];
    float* out = (float*)d_out;

    cudaFuncSetAttribute(prep_E_kernel, cudaFuncAttributeMaxDynamicSharedMemorySize, SMEM128);
    cudaFuncSetAttribute(gates_tc, cudaFuncAttributeMaxDynamicSharedMemorySize, SMEM128);
    cudaFuncSetAttribute(logits_tc, cudaFuncAttributeMaxDynamicSharedMemorySize, SMEM64);

    prep_gates<<<(G4H * HID) / 256, 256>>>(W_ih, W_hh, b_ih, b_hh);
    prep_out<<<(VOCAB * HID) / 256, 256>>>(W_out, emb);
    init_state_tc<<<(BATCH * HID) / 256, 256>>>(enc_h, enc_c);
    prep_E_kernel<<<dim3(16, 4), 256, SMEM128>>>();

    for (int t = 0; t < T_STEPS; t++) {
        int rd = t & 1;
        gates_tc<<<dim3(16, 8), 256, SMEM128>>>(rd);
        float* logits_t = out + (size_t)t * BATCH * VOCAB;
        logits_tc<<<dim3(8, 16), 256, SMEM64>>>(rd ^ 1, rd, b_out, logits_t);
    }
}